// round 17
// baseline (speedup 1.0000x reference)
#include <cuda_runtime.h>
#include <math.h>

#define TT 512
#define DD 512
#define NBATCH 2
#define VV 256
#define MMEM 256
#define BT 1024
#define D3 1536
#define DOM_BLOCKS 64
#define UNITS 8
#define GRU_THREADS 384

// ---------------- static device scratch ----------------
__device__ float g_table[VV * D3];
__device__ float g_ps[BT * DD];
__device__ float g_qkv[BT * D3];
__device__ float g_S[NBATCH * TT * TT];
__device__ float g_den[BT];
__device__ float g_attn[BT * MMEM];
__device__ float g_comb[BT * 2048];
__device__ float g_tpre[BT * DD];
__device__ float g_gatepre[BT * DD];
__device__ float g_qh[BT * DD];
__device__ float g_wnorm[VV];
__device__ float g_hf3[3][NBATCH * DD];
__device__ float g_hs3[3][NBATCH * DD];
__device__ unsigned g_barb[2][32];

// ---------------- block reductions ----------------
__device__ __forceinline__ float block_red_sum(float v, float* sb) {
    __syncthreads();
    int lane = threadIdx.x & 31, w = threadIdx.x >> 5;
    #pragma unroll
    for (int o = 16; o; o >>= 1) v += __shfl_xor_sync(0xffffffffu, v, o);
    if (lane == 0) sb[w] = v;
    __syncthreads();
    float r = (lane < (int)(blockDim.x >> 5)) ? sb[lane] : 0.f;
    #pragma unroll
    for (int o = 16; o; o >>= 1) r += __shfl_xor_sync(0xffffffffu, r, o);
    return r;
}

__device__ __forceinline__ float block_red_max(float v, float* sb) {
    __syncthreads();
    int lane = threadIdx.x & 31, w = threadIdx.x >> 5;
    #pragma unroll
    for (int o = 16; o; o >>= 1) v = fmaxf(v, __shfl_xor_sync(0xffffffffu, v, o));
    if (lane == 0) sb[w] = v;
    __syncthreads();
    float r = (lane < (int)(blockDim.x >> 5)) ? sb[lane] : -3.4e38f;
    #pragma unroll
    for (int o = 16; o; o >>= 1) r = fmaxf(r, __shfl_xor_sync(0xffffffffu, r, o));
    return r;
}

// reset barrier counters AND zero g_den (runs before the GRU each replay)
__global__ void reset_bar_kernel() {
    if (threadIdx.x == 0) { g_barb[0][0] = 0u; g_barb[1][0] = 0u; }
    if (threadIdx.x < 1024) g_den[threadIdx.x] = 0.f;
}

// ---------------- fast activations ----------------
__device__ __forceinline__ float sigf(float x) {
    return __fdividef(1.f, 1.f + __expf(-x));
}
__device__ __forceinline__ float tanhf_fast(float x) {
    float ax = fabsf(x);
    float t = __expf(-2.f * ax);
    float r = __fdividef(1.f - t, 1.f + t);
    return copysignf(r, x);
}

#define FMA2(d, a, b, c) \
    asm("fma.rn.f32x2 %0, %1, %2, %3;" : "=l"(d) : "l"(a), "l"(b), "l"(c))

// ---------------- batch-split fused GRU (staggered loads, no pf array) ----------------
__global__ void __launch_bounds__(GRU_THREADS) fused_gru_kernel(
    const float* __restrict__ fast_whh, const float* __restrict__ fast_bhh,
    const float* __restrict__ slow_wih, const float* __restrict__ slow_bih,
    const float* __restrict__ slow_whh, const float* __restrict__ slow_bhh,
    const float* __restrict__ gi_table, const int* __restrict__ toks,
    const float* __restrict__ hf0, const float* __restrict__ hs0,
    float* __restrict__ comb, float* __restrict__ ps,
    float* __restrict__ hfT, float* __restrict__ hsT)
{
    __shared__ float sg[3][3][UNITS];
    const int tid = threadIdx.x;
    const int w = tid >> 5, lane = tid & 31;
    const int dom = blockIdx.x >> 6;
    const int blk = blockIdx.x & 63;
    const int ibase = blk * UNITS;
    const int tr = w >> 2, up = w & 3;
    unsigned* barp = &g_barb[dom][0];

    const float* Wsrc = (tr == 0) ? fast_whh : ((tr == 1) ? slow_wih : slow_whh);
    ulonglong2 wreg[2][3][4];
    #pragma unroll
    for (int uu = 0; uu < 2; uu++) {
        const int u = ibase + up * 2 + uu;
        #pragma unroll
        for (int g = 0; g < 3; g++)
            #pragma unroll
            for (int j = 0; j < 4; j++)
                wreg[uu][g][j] = *(const ulonglong2*)&Wsrc[(size_t)(g * DD + u) * DD + lane * 4 + j * 128];
    }

    const int ci = ibase + lane;
    float b_r = 0.f, b_z = 0.f, b_n = 0.f;
    float b2_r = 0.f, b2_z = 0.f, b2_n = 0.f;
    float hprev = 0.f;
    if (w == 0 && lane < 8) {
        b_r = fast_bhh[ci]; b_z = fast_bhh[DD + ci]; b_n = fast_bhh[2 * DD + ci];
        hprev = hf0[dom * DD + ci];
        g_hf3[0][dom * DD + ci] = hprev;
    }
    if (w == 1 && lane < 8) {
        b_r = slow_bih[ci]; b_z = slow_bih[DD + ci]; b_n = slow_bih[2 * DD + ci];
        b2_r = slow_bhh[ci]; b2_z = slow_bhh[DD + ci]; b2_n = slow_bhh[2 * DD + ci];
        hprev = hs0[dom * DD + ci];
        g_hs3[0][dom * DD + ci] = hprev;
    }
    __syncthreads();
    if (tid == 0) {
        asm volatile("red.release.gpu.global.add.u32 [%0], 1;" :: "l"(barp) : "memory");
        unsigned v;
        do {
            asm volatile("ld.acquire.gpu.u32 %0, [%1];" : "=r"(v) : "l"(barp) : "memory");
        } while (v < DOM_BLOCKS);
    }
    __syncthreads();

    const int jrot = (w + blk) & 3;     // per-warp/block load-order stagger

    for (int t = 0; t <= TT; t++) {
        const int cur = t % 3, nxt = (t + 1) % 3;
        const int cur_s = (t + 2) % 3, nxt_s = t % 3;

        float gr = 0.f, gz = 0.f, gn = 0.f;
        if (w == 0 && lane < 8 && t < TT) {
            const int row = dom * TT + t;
            const float* gi = gi_table + (size_t)__ldg(&toks[row]) * D3;
            gr = __ldg(gi + ci); gz = __ldg(gi + DD + ci); gn = __ldg(gi + 2 * DD + ci);
        }

        const float* base;
        if (tr == 0)      base = &g_hf3[cur][dom * DD];
        else if (tr == 1) base = comb + (size_t)(dom * TT + ((t > 0) ? t - 1 : 0)) * 2048;
        else              base = &g_hs3[cur_s][dom * DD];
        ulonglong2 xv[4];
        #pragma unroll
        for (int jj = 0; jj < 4; jj++) {
            const int j = (jj + jrot) & 3;
            xv[j] = __ldcg((const ulonglong2*)(base + lane * 4 + j * 128));
        }

        unsigned long long acc2[2][3];
        #pragma unroll
        for (int uu = 0; uu < 2; uu++)
            #pragma unroll
            for (int g = 0; g < 3; g++) acc2[uu][g] = 0ull;
        #pragma unroll
        for (int j = 0; j < 4; j++)
            #pragma unroll
            for (int uu = 0; uu < 2; uu++)
                #pragma unroll
                for (int g = 0; g < 3; g++) {
                    FMA2(acc2[uu][g], wreg[uu][g][j].x, xv[j].x, acc2[uu][g]);
                    FMA2(acc2[uu][g], wreg[uu][g][j].y, xv[j].y, acc2[uu][g]);
                }

        float a[2][3];
        #pragma unroll
        for (int uu = 0; uu < 2; uu++)
            #pragma unroll
            for (int g = 0; g < 3; g++) {
                float lo, hi;
                asm("mov.b64 {%0, %1}, %2;" : "=f"(lo), "=f"(hi) : "l"(acc2[uu][g]));
                a[uu][g] = lo + hi;
            }
        #pragma unroll
        for (int o = 16; o; o >>= 1)
            #pragma unroll
            for (int uu = 0; uu < 2; uu++)
                #pragma unroll
                for (int g = 0; g < 3; g++)
                    a[uu][g] += __shfl_xor_sync(0xffffffffu, a[uu][g], o);

        if (lane == 0) {
            #pragma unroll
            for (int uu = 0; uu < 2; uu++)
                #pragma unroll
                for (int g = 0; g < 3; g++)
                    sg[tr][g][up * 2 + uu] = a[uu][g];
        }
        __syncthreads();

        if (w == 0 && lane < 8 && t < TT) {
            const int row = dom * TT + t;
            float r = sigf(gr + sg[0][0][lane] + b_r);
            float z = sigf(gz + sg[0][1][lane] + b_z);
            float n = tanhf_fast(gn + r * (sg[0][2][lane] + b_n));
            float hnew = (1.f - z) * n + z * hprev;
            hprev = hnew;
            g_hf3[nxt][dom * DD + ci] = hnew;
            comb[(size_t)row * 2048 + ci] = hnew;
            if (t == TT - 1) hfT[dom * DD + ci] = hnew;
        }
        if (w == 1 && lane < 8 && t >= 1) {
            const int ts = t - 1, row = dom * TT + ts;
            float r = sigf(sg[1][0][lane] + b_r + sg[2][0][lane] + b2_r);
            float z = sigf(sg[1][1][lane] + b_z + sg[2][1][lane] + b2_z);
            float n = tanhf_fast(sg[1][2][lane] + b_n + r * (sg[2][2][lane] + b2_n));
            float hnew = (1.f - z) * n + z * hprev;
            hprev = hnew;
            g_hs3[nxt_s][dom * DD + ci] = hnew;
            ps[(size_t)row * DD + ci] = hnew;
            if (ts == TT - 1) hsT[dom * DD + ci] = hnew;
        }
        if (t < TT) {
            __syncthreads();
            if (tid == 0) {
                asm volatile("red.release.gpu.global.add.u32 [%0], 1;" :: "l"(barp) : "memory");
                unsigned target = (unsigned)(t + 2) * DOM_BLOCKS;
                unsigned v;
                do {
                    asm volatile("ld.acquire.gpu.u32 %0, [%1];" : "=r"(v) : "l"(barp) : "memory");
                } while (v < target);
            }
            __syncthreads();
        }
    }
}

// ---------------- GEMM: MT x 64 tile, 256 thr, f32x2 FMA ----------------
// TB: Bm stored [N,K]; else [K,N]. CAUSAL: tile-cull + mask. klim: Kc=m0+MT.
// elu_cols: elu+1 on cols < elu_cols. colscale: per-col multiplier.
// den_acc: atomicAdd masked row-sums into g_den[z*512+mm].
// rowdiv: multiply output row by 1/(g_den[z*512+mm]+1e-6).
template <int MT, bool TB, bool CAUSAL>
__global__ void __launch_bounds__(256) gemm_kernel(
    const float* __restrict__ A, const float* __restrict__ Bm,
    const float* __restrict__ bias, float* __restrict__ C,
    int M, int N, int K, int lda, int ldb, int ldc,
    long long sA, long long sB, long long sC, long long sBias,
    float scale, int klim, int elu_cols, const float* __restrict__ colscale,
    int den_acc, int rowdiv)
{
    constexpr int RP = MT / 32;
    __shared__ __align__(16) float As[2][16][MT + 4];
    __shared__ __align__(16) float Bs[2][16][68];
    const int z = blockIdx.z;
    A += (size_t)z * sA; Bm += (size_t)z * sB; C += (size_t)z * sC;
    if (bias) bias += (size_t)z * sBias;
    const int m0 = blockIdx.y * MT, n0 = blockIdx.x * 64;
    const int tid = threadIdx.x;
    const int ty = tid >> 4, tx = tid & 15;
    const int nn = n0 + (tx << 2);

    if (CAUSAL && n0 > m0 + MT - 1) {
        float4 zv = make_float4(0.f, 0.f, 0.f, 0.f);
        #pragma unroll
        for (int p2 = 0; p2 < RP; p2++)
            #pragma unroll
            for (int half = 0; half < 2; half++) {
                const int mm = m0 + ty * 2 * RP + (p2 << 1) + half;
                *(float4*)(C + (size_t)mm * ldc + nn) = zv;
            }
        return;
    }

    const int Kc = klim ? ((m0 + MT < K) ? m0 + MT : K) : K;
    const int ar = tid >> 2, ac = (tid & 3) << 2;
    const int bk = tid >> 4, bn = (tid & 15) << 2;

    float4 a0 = *(const float4*)(A + (size_t)(m0 + ar) * lda + ac);
    float4 a1;
    if (MT == 128) a1 = *(const float4*)(A + (size_t)(m0 + ar + 64) * lda + ac);
    float4 bv;
    if (TB) bv = *(const float4*)(Bm + (size_t)(n0 + ar) * ldb + ac);
    else    bv = *(const float4*)(Bm + (size_t)bk * ldb + n0 + bn);

    {
        As[0][ac + 0][ar] = a0.x; As[0][ac + 1][ar] = a0.y;
        As[0][ac + 2][ar] = a0.z; As[0][ac + 3][ar] = a0.w;
        if (MT == 128) {
            As[0][ac + 0][ar + 64] = a1.x; As[0][ac + 1][ar + 64] = a1.y;
            As[0][ac + 2][ar + 64] = a1.z; As[0][ac + 3][ar + 64] = a1.w;
        }
        if (TB) {
            Bs[0][ac + 0][ar] = bv.x; Bs[0][ac + 1][ar] = bv.y;
            Bs[0][ac + 2][ar] = bv.z; Bs[0][ac + 3][ar] = bv.w;
        } else {
            *(float4*)&Bs[0][bk][bn] = bv;
        }
    }
    __syncthreads();

    unsigned long long acc[RP][4];
    #pragma unroll
    for (int p2 = 0; p2 < RP; p2++)
        #pragma unroll
        for (int jj = 0; jj < 4; jj++) acc[p2][jj] = 0ull;

    const int P = Kc >> 4;
    int buf = 0;
    for (int p = 0; p < P; p++) {
        if (p + 1 < P) {
            const int k0n = (p + 1) << 4;
            a0 = *(const float4*)(A + (size_t)(m0 + ar) * lda + k0n + ac);
            if (MT == 128) a1 = *(const float4*)(A + (size_t)(m0 + ar + 64) * lda + k0n + ac);
            if (TB) bv = *(const float4*)(Bm + (size_t)(n0 + ar) * ldb + k0n + ac);
            else    bv = *(const float4*)(Bm + (size_t)(k0n + bk) * ldb + n0 + bn);
        }
        #pragma unroll
        for (int k = 0; k < 16; k++) {
            ulonglong2 af[RP / 2];
            af[0] = *(const ulonglong2*)&As[buf][k][ty * 2 * RP];
            if (RP == 4) af[1] = *(const ulonglong2*)&As[buf][k][ty * 2 * RP + 4];
            float4 b4 = *(const float4*)&Bs[buf][k][tx << 2];
            unsigned long long bd[4];
            asm("mov.b64 %0, {%1, %1};" : "=l"(bd[0]) : "f"(b4.x));
            asm("mov.b64 %0, {%1, %1};" : "=l"(bd[1]) : "f"(b4.y));
            asm("mov.b64 %0, {%1, %1};" : "=l"(bd[2]) : "f"(b4.z));
            asm("mov.b64 %0, {%1, %1};" : "=l"(bd[3]) : "f"(b4.w));
            #pragma unroll
            for (int p2 = 0; p2 < RP; p2++) {
                unsigned long long av = (p2 & 1) ? af[p2 >> 1].y : af[p2 >> 1].x;
                #pragma unroll
                for (int jj = 0; jj < 4; jj++)
                    FMA2(acc[p2][jj], av, bd[jj], acc[p2][jj]);
            }
        }
        if (p + 1 < P) {
            const int nb = buf ^ 1;
            As[nb][ac + 0][ar] = a0.x; As[nb][ac + 1][ar] = a0.y;
            As[nb][ac + 2][ar] = a0.z; As[nb][ac + 3][ar] = a0.w;
            if (MT == 128) {
                As[nb][ac + 0][ar + 64] = a1.x; As[nb][ac + 1][ar + 64] = a1.y;
                As[nb][ac + 2][ar + 64] = a1.z; As[nb][ac + 3][ar + 64] = a1.w;
            }
            if (TB) {
                Bs[nb][ac + 0][ar] = bv.x; Bs[nb][ac + 1][ar] = bv.y;
                Bs[nb][ac + 2][ar] = bv.z; Bs[nb][ac + 3][ar] = bv.w;
            } else {
                *(float4*)&Bs[nb][bk][bn] = bv;
            }
            __syncthreads();
            buf = nb;
        }
    }

    float4 bvec;
    if (bias) bvec = *(const float4*)&bias[nn];
    float4 csv;
    if (colscale) csv = *(const float4*)&colscale[nn];
    #pragma unroll
    for (int p2 = 0; p2 < RP; p2++) {
        float rlo[4], rhi[4];
        #pragma unroll
        for (int jj = 0; jj < 4; jj++) {
            float lo, hi;
            asm("mov.b64 {%0, %1}, %2;" : "=f"(lo), "=f"(hi) : "l"(acc[p2][jj]));
            rlo[jj] = lo; rhi[jj] = hi;
        }
        #pragma unroll
        for (int half = 0; half < 2; half++) {
            const int mm = m0 + ty * 2 * RP + (p2 << 1) + half;
            float* rr = half ? rhi : rlo;
            float4 cv;
            cv.x = rr[0] * scale; cv.y = rr[1] * scale;
            cv.z = rr[2] * scale; cv.w = rr[3] * scale;
            if (colscale) { cv.x *= csv.x; cv.y *= csv.y; cv.z *= csv.z; cv.w *= csv.w; }
            if (bias) { cv.x += bvec.x; cv.y += bvec.y; cv.z += bvec.z; cv.w += bvec.w; }
            if (elu_cols) {
                if (nn + 0 < elu_cols) cv.x = cv.x > 0.f ? cv.x + 1.f : __expf(cv.x);
                if (nn + 1 < elu_cols) cv.y = cv.y > 0.f ? cv.y + 1.f : __expf(cv.y);
                if (nn + 2 < elu_cols) cv.z = cv.z > 0.f ? cv.z + 1.f : __expf(cv.z);
                if (nn + 3 < elu_cols) cv.w = cv.w > 0.f ? cv.w + 1.f : __expf(cv.w);
            }
            if (CAUSAL) {
                if (nn + 0 > mm) cv.x = 0.f;
                if (nn + 1 > mm) cv.y = 0.f;
                if (nn + 2 > mm) cv.z = 0.f;
                if (nn + 3 > mm) cv.w = 0.f;
            }
            if (rowdiv) {
                float inv = __fdividef(1.f, g_den[z * 512 + mm] + 1e-6f);
                cv.x *= inv; cv.y *= inv; cv.z *= inv; cv.w *= inv;
            }
            *(float4*)(C + (size_t)mm * ldc + nn) = cv;
            if (den_acc) {
                float rs = cv.x + cv.y + cv.z + cv.w;
                #pragma unroll
                for (int o = 8; o; o >>= 1) rs += __shfl_xor_sync(0xffffffffu, rs, o);
                if (tx == 0) atomicAdd(&g_den[z * 512 + mm], rs);
            }
        }
    }
}

// ---------------- small kernels ----------------
__global__ void softmax_kernel() {
    __shared__ float sb[32];
    int row = blockIdx.x;
    float x = g_attn[(size_t)row * MMEM + threadIdx.x];
    float m = block_red_max(x, sb);
    float e = __expf(x - m);
    float s = block_red_sum(e, sb);
    g_attn[(size_t)row * MMEM + threadIdx.x] = e / s;
}

__device__ __forceinline__ float tanh_bulk(float x) {
    float ax = fabsf(x);
    float t = __expf(-2.f * ax);
    float r = __fdividef(1.f - t, 1.f + t);
    return copysignf(r, x);
}

// mode 0: out = tanh(LN(in));  mode 1: out = LN(tanh(in))
__global__ void ln_kernel(const float* __restrict__ in, const float* __restrict__ gg,
                          const float* __restrict__ bb, float* __restrict__ out,
                          int ldo, int mode)
{
    __shared__ float sb[32];
    int row = blockIdx.x, tid = threadIdx.x;
    float x0 = in[(size_t)row * DD + tid];
    float x1 = in[(size_t)row * DD + 256 + tid];
    if (mode == 1) { x0 = tanh_bulk(x0); x1 = tanh_bulk(x1); }
    float s  = block_red_sum(x0 + x1, sb);
    float sq = block_red_sum(x0 * x0 + x1 * x1, sb);
    float mean = s * (1.f / 512.f);
    float var  = sq * (1.f / 512.f) - mean * mean;
    float rstd = rsqrtf(var + 1e-5f);
    float y0 = (x0 - mean) * rstd * gg[tid] + bb[tid];
    float y1 = (x1 - mean) * rstd * gg[256 + tid] + bb[256 + tid];
    if (mode == 0) { y0 = tanh_bulk(y0); y1 = tanh_bulk(y1); }
    out[(size_t)row * ldo + tid] = y0;
    out[(size_t)row * ldo + 256 + tid] = y1;
}

__global__ void rownorm_kernel(const float* __restrict__ src) {
    __shared__ float sb[32];
    int row = blockIdx.x, tid = threadIdx.x;
    float x0 = src[(size_t)row * DD + tid];
    float x1 = src[(size_t)row * DD + 256 + tid];
    float ss = block_red_sum(x0 * x0 + x1 * x1, sb);
    if (tid == 0) g_wnorm[row] = 16.f / fmaxf(sqrtf(ss), 1e-12f);
}

// ---------------- host ----------------
static inline void gemm(const float* A, const float* B, const float* bias, float* C,
                        int M, int N, int K, int lda, int ldb, int ldc,
                        float scale, int batch, long long sA, long long sB, long long sC,
                        int mt, bool tb, bool causal, int klim = 0, int elu_cols = 0,
                        long long sBias = 0, const float* colscale = nullptr,
                        int den_acc = 0, int rowdiv = 0)
{
    dim3 grid(N / 64, M / mt, batch);
    if (mt == 128) {
        if (tb) {
            if (causal) gemm_kernel<128, true, true><<<grid, 256>>>(A, B, bias, C, M, N, K, lda, ldb, ldc, sA, sB, sC, sBias, scale, klim, elu_cols, colscale, den_acc, rowdiv);
            else        gemm_kernel<128, true, false><<<grid, 256>>>(A, B, bias, C, M, N, K, lda, ldb, ldc, sA, sB, sC, sBias, scale, klim, elu_cols, colscale, den_acc, rowdiv);
        } else {
            gemm_kernel<128, false, false><<<grid, 256>>>(A, B, bias, C, M, N, K, lda, ldb, ldc, sA, sB, sC, sBias, scale, klim, elu_cols, colscale, den_acc, rowdiv);
        }
    } else {
        if (tb) {
            if (causal) gemm_kernel<64, true, true><<<grid, 256>>>(A, B, bias, C, M, N, K, lda, ldb, ldc, sA, sB, sC, sBias, scale, klim, elu_cols, colscale, den_acc, rowdiv);
            else        gemm_kernel<64, true, false><<<grid, 256>>>(A, B, bias, C, M, N, K, lda, ldb, ldc, sA, sB, sC, sBias, scale, klim, elu_cols, colscale, den_acc, rowdiv);
        } else {
            gemm_kernel<64, false, false><<<grid, 256>>>(A, B, bias, C, M, N, K, lda, ldb, ldc, sA, sB, sC, sBias, scale, klim, elu_cols, colscale, den_acc, rowdiv);
        }
    }
}

extern "C" void kernel_launch(void* const* d_in, const int* in_sizes, int n_in,
                              void* d_out, int out_size)
{
    (void)in_sizes; (void)n_in; (void)out_size;
    const int*   x        = (const int*)d_in[0];
    const float* h_f      = (const float*)d_in[1];
    const float* h_s      = (const float*)d_in[2];
    const float* soma_w   = (const float*)d_in[3];
    const float* fast_wih = (const float*)d_in[4];
    const float* fast_whh = (const float*)d_in[5];
    const float* fast_bih = (const float*)d_in[6];
    const float* fast_bhh = (const float*)d_in[7];
    const float* slow_wih = (const float*)d_in[8];
    const float* slow_whh = (const float*)d_in[9];
    const float* slow_bih = (const float*)d_in[10];
    const float* slow_bhh = (const float*)d_in[11];
    const float* qkv_w    = (const float*)d_in[12];
    const float* qkv_b    = (const float*)d_in[13];
    const float* gate_w   = (const float*)d_in[14];
    const float* gate_b   = (const float*)d_in[15];
    const float* gate_g   = (const float*)d_in[16];
    const float* gate_bb  = (const float*)d_in[17];
    const float* mem_bank = (const float*)d_in[18];
    const float* hip_qw   = (const float*)d_in[19];
    const float* hip_qb   = (const float*)d_in[20];
    const float* axon_w   = (const float*)d_in[21];
    const float* axon_b   = (const float*)d_in[22];
    const float* norm_g   = (const float*)d_in[23];
    const float* norm_b   = (const float*)d_in[24];

    float* out = (float*)d_out;
    float* out_logits  = out;            // [B,T,V]
    float* out_thought = out + 262144;   // [B,T,D]
    float* out_hf      = out + 786432;   // [1,B,D]
    float* out_hs      = out + 787456;   // [1,B,D]

    float *p_table, *p_ps, *p_qkv, *p_S, *p_attn, *p_comb,
          *p_tpre, *p_gatepre, *p_qh, *p_wnorm;
    cudaGetSymbolAddress((void**)&p_table,   g_table);
    cudaGetSymbolAddress((void**)&p_ps,      g_ps);
    cudaGetSymbolAddress((void**)&p_qkv,     g_qkv);
    cudaGetSymbolAddress((void**)&p_S,       g_S);
    cudaGetSymbolAddress((void**)&p_attn,    g_attn);
    cudaGetSymbolAddress((void**)&p_comb,    g_comb);
    cudaGetSymbolAddress((void**)&p_tpre,    g_tpre);
    cudaGetSymbolAddress((void**)&p_gatepre, g_gatepre);
    cudaGetSymbolAddress((void**)&p_qh,      g_qh);
    cudaGetSymbolAddress((void**)&p_wnorm,   g_wnorm);

    // per-row 16/||soma_w|| for the logits epilogue
    rownorm_kernel<<<VV, 256>>>(soma_w);

    // fast-GRU input-gate token table
    gemm(soma_w, fast_wih, fast_bih, p_table, 256, 1536, 512, 512, 512, 1536,
         1.f, 1, 0, 0, 0, 64, true, false);

    // reset counters + zero den
    reset_bar_kernel<<<1, 1024>>>();

    // batch-split fused GRUs -> comb[:,0:512], p_s, hf1, hs1
    fused_gru_kernel<<<2 * DOM_BLOCKS, GRU_THREADS>>>(
        fast_whh, fast_bhh, slow_wih, slow_bih, slow_whh, slow_bhh,
        p_table, x, h_f, h_s, p_comb, p_ps, out_hf, out_hs);

    // qkv projection (elu fused for q,k cols)
    gemm(p_ps, qkv_w, qkv_b, p_qkv, 1024, 1536, 512, 512, 512, 1536,
         1.f, 1, 0, 0, 0, 64, true, false, 0, 1024);

    // gate + hip projections (batched: z=0 gate, z=1 hip)
    gemm(p_ps, gate_w, gate_b, p_gatepre, 1024, 512, 512, 512, 512, 512,
         1.f, 2, 0, (long long)(hip_qw - gate_w), (long long)(p_qh - p_gatepre),
         64, true, false, 0, 0, (long long)(hip_qb - gate_b));

    // S = q k^T (causal, culled) + den row-sums in epilogue
    gemm(p_qkv, p_qkv + 512, nullptr, p_S, 512, 512, 512, 1536, 1536, 512,
         1.f, 2, 512LL * 1536, 512LL * 1536, 512LL * 512, 64, true, true,
         0, 0, 0, nullptr, 1, 0);
    // num = S @ v, divided by den in epilogue -> combined[:, 1024:1536]
    gemm(p_S, p_qkv + 1024, nullptr, p_comb + 1024, 512, 512, 512, 512, 1536, 2048,
         1.f, 2, 512LL * 512, 512LL * 1536, 512LL * 2048, 64, false, false,
         1, 0, 0, nullptr, 0, 1);

    // intent = tanh(LN(gatepre)) -> combined[:, 512:1024]
    ln_kernel<<<BT, 256>>>(p_gatepre, gate_g, gate_bb, p_comb + 512, 2048, 0);

    // hippocampus: attn = softmax(qh @ mem^T / sqrt(D)); episodes = attn @ mem
    gemm(p_qh, mem_bank, nullptr, p_attn, 1024, 256, 512, 512, 512, 256,
         0.044194173824159216f, 1, 0, 0, 0, 64, true, false);
    softmax_kernel<<<BT, 256>>>();
    gemm(p_attn, mem_bank, nullptr, p_comb + 1536, 1024, 512, 256, 256, 512, 2048,
         1.f, 1, 0, 0, 0, 64, false, false);

    // thought = LN(tanh(combined @ axon_w^T + axon_b))
    gemm(p_comb, axon_w, axon_b, p_tpre, 1024, 512, 2048, 2048, 2048, 512,
         1.f, 1, 0, 0, 0, 64, true, false);
    ln_kernel<<<BT, 256>>>(p_tpre, norm_g, norm_b, out_thought, 512, 1);

    // logits = (thought @ soma_w^T) * (16/||soma_w_row||)
    gemm(out_thought, soma_w, nullptr, out_logits, 1024, 256, 512, 512, 512, 256,
         1.f, 1, 0, 0, 0, 64, true, false, 0, 0, 0, p_wnorm);
}